// round 4
// baseline (speedup 1.0000x reference)
#include <cuda_runtime.h>
#include <cuda_bf16.h>
#include <cstdint>
#include <math.h>

#define NPTS 8192
#define DEMB 1024
#define NT   64            // 128-wide tiles per dim
#define NTILES 2080        // NT*(NT+1)/2 upper-triangular tiles

// ---------------- scratch (device globals: no allocations allowed) ----------
__device__ __align__(128) __nv_bfloat16 g_hi[(size_t)NPTS * DEMB];   // 16 MB
__device__ __align__(128) __nv_bfloat16 g_lo[(size_t)NPTS * DEMB];   // 16 MB
__device__ __align__(128) float         g_sq[NPTS];
__device__ __align__(128) unsigned char g_tgt[NPTS];
__device__ __align__(128) float         g_Dm[(size_t)NPTS * NPTS];   // 256 MB
__device__ __align__(128) int           g_pos[NPTS];
__device__ __align__(128) int           g_neg[NPTS];
__device__ __align__(128) float         g_loss[NPTS];

// ---------------- ptx helpers ----------------------------------------------
__device__ __forceinline__ uint32_t smem_u32(const void* p) {
    uint32_t a;
    asm("{ .reg .u64 t; cvta.to.shared.u64 t, %1; cvt.u32.u64 %0, t; }"
        : "=r"(a) : "l"(p));
    return a;
}

__device__ __forceinline__ void cp16(uint32_t s, const void* g) {
    asm volatile("cp.async.cg.shared.global [%0], [%1], 16;" :: "r"(s), "l"(g));
}
__device__ __forceinline__ void cp_commit() {
    asm volatile("cp.async.commit_group;" ::: "memory");
}

__device__ __forceinline__ void ldsm4(uint32_t addr, uint32_t* r) {
    asm volatile("ldmatrix.sync.aligned.m8n8.x4.shared.b16 {%0,%1,%2,%3}, [%4];"
        : "=r"(r[0]), "=r"(r[1]), "=r"(r[2]), "=r"(r[3]) : "r"(addr));
}

__device__ __forceinline__ void mma16816(float* c, const uint32_t* a, const uint32_t* b) {
    asm volatile(
        "mma.sync.aligned.m16n8k16.row.col.f32.bf16.bf16.f32 "
        "{%0,%1,%2,%3},{%4,%5,%6,%7},{%8,%9},{%0,%1,%2,%3};"
        : "+f"(c[0]), "+f"(c[1]), "+f"(c[2]), "+f"(c[3])
        : "r"(a[0]), "r"(a[1]), "r"(a[2]), "r"(a[3]), "r"(b[0]), "r"(b[1]));
}

// ---------------- phase 0: convert to hi/lo bf16 split ---------------------
__global__ void __launch_bounds__(256) conv_kernel(const float* __restrict__ emb) {
    size_t idx = (size_t)blockIdx.x * 256 + threadIdx.x;
    float e = emb[idx];
    __nv_bfloat16 h = __float2bfloat16(e);
    g_hi[idx] = h;
    g_lo[idx] = __float2bfloat16(e - __bfloat162float(h));
}

// ---------------- phase 0b: row squared norms + target u8 ------------------
__global__ void __launch_bounds__(256) sq_kernel(const float* __restrict__ emb,
                                                 const int* __restrict__ tgt) {
    int row = blockIdx.x * 8 + (threadIdx.x >> 5);
    int lid = threadIdx.x & 31;
    const float4* r4 = (const float4*)(emb + (size_t)row * DEMB);
    float s = 0.f;
#pragma unroll
    for (int k = 0; k < 8; k++) {
        float4 v = r4[lid + k * 32];
        s += v.x * v.x + v.y * v.y + v.z * v.z + v.w * v.w;
    }
#pragma unroll
    for (int o = 16; o; o >>= 1) s += __shfl_down_sync(0xffffffffu, s, o);
    if (lid == 0) {
        g_sq[row] = s;
        g_tgt[row] = (unsigned char)tgt[row];
    }
}

// ---------------- phase B: mma.sync GEMM + distance epilogue ---------------
// CTA computes a 128x128 tile of the symmetric distance matrix at (by, bx),
// by <= bx (triangular decode of blockIdx.x); off-diagonal tiles also write
// the mirrored (bx, by) tile via an smem transpose.
//
// Smem layout per stage (stride 40960): Ahi @0, Alo @10240, Bhi @20480,
// Blo @30720. Each tile: 128 rows x 80B (32 bf16 payload, 5x16B rows ->
// conflict-free ldmatrix). 2 stages = 81920 B dynamic smem.

__global__ void __launch_bounds__(256) gemm_kernel() {
    extern __shared__ __align__(16) char rawsm[];
    char* dyns = (char*)(((uintptr_t)rawsm + 127) & ~(uintptr_t)127);
    __shared__ float s_sqi[128];
    __shared__ float s_sqj[128];

    const int tid  = threadIdx.x;
    const int lane = tid & 31;
    const int wid  = tid >> 5;

    // decode triangular tile index
    int t = blockIdx.x;
    int by = 0;
    while (t >= NT - by) { t -= NT - by; by++; }
    const int bx = by + t;
    const int i0 = by * 128;
    const int j0 = bx * 128;

    if (tid < 128) s_sqi[tid] = g_sq[i0 + tid];
    else           s_sqj[tid - 128] = g_sq[j0 + tid - 128];

    const int wm = (wid & 3) * 32;   // warp m-offset in CTA tile
    const int wn = (wid >> 2) * 64;  // warp n-offset

    const uint32_t sbase = smem_u32(dyns);

    // per-thread global/smem load mapping: task = p*256+tid -> (row, 16B chunk)
    const int r0l = tid >> 2;            // rows 0..63   (p=0)
    const int r1l = (256 + tid) >> 2;    // rows 64..127 (p=1)
    const int cl  = tid & 3;

    // prologue: stage 0
    {
        uint32_t st = sbase;
#pragma unroll
        for (int p = 0; p < 2; ++p) {
            int r = p ? r1l : r0l;
            uint32_t so = r * 80 + cl * 16;
            size_t ga = (size_t)(i0 + r) * DEMB + cl * 8;
            size_t gb = (size_t)(j0 + r) * DEMB + cl * 8;
            cp16(st + so,         g_hi + ga);
            cp16(st + 10240 + so, g_lo + ga);
            cp16(st + 20480 + so, g_hi + gb);
            cp16(st + 30720 + so, g_lo + gb);
        }
        cp_commit();
    }

    float acc[2][8][4];
#pragma unroll
    for (int a = 0; a < 2; ++a)
#pragma unroll
        for (int b = 0; b < 8; ++b)
#pragma unroll
            for (int c = 0; c < 4; ++c) acc[a][b][c] = 0.f;

    // per-thread ldmatrix address components
    const uint32_t a_row   = (uint32_t)(lane & 15);
    const uint32_t a_coff  = (uint32_t)(((lane >> 4) & 1) * 16);
    const uint32_t b_row   = (uint32_t)((lane & 7) + ((lane & 16) >> 1));
    const uint32_t b_coff  = (uint32_t)((lane & 8) << 1);

    for (int kc = 0; kc < 32; ++kc) {
        const int cur = kc & 1;
        if (kc + 1 < 32) {
            uint32_t st = sbase + (cur ^ 1) * 40960;
            const int k0 = (kc + 1) * 32;
#pragma unroll
            for (int p = 0; p < 2; ++p) {
                int r = p ? r1l : r0l;
                uint32_t so = r * 80 + cl * 16;
                size_t ga = (size_t)(i0 + r) * DEMB + k0 + cl * 8;
                size_t gb = (size_t)(j0 + r) * DEMB + k0 + cl * 8;
                cp16(st + so,         g_hi + ga);
                cp16(st + 10240 + so, g_lo + ga);
                cp16(st + 20480 + so, g_hi + gb);
                cp16(st + 30720 + so, g_lo + gb);
            }
            cp_commit();
            asm volatile("cp.async.wait_group 1;" ::: "memory");
        } else {
            asm volatile("cp.async.wait_group 0;" ::: "memory");
        }
        __syncthreads();

        const uint32_t st = sbase + cur * 40960;
#pragma unroll
        for (int ks = 0; ks < 2; ++ks) {
            const uint32_t ko = ks * 32;
            uint32_t ah[2][4], al[2][4], bb[4][4];
#pragma unroll
            for (int mf = 0; mf < 2; ++mf) {
                uint32_t rr = (wm + mf * 16 + a_row) * 80 + ko + a_coff;
                ldsm4(st + rr,         ah[mf]);
                ldsm4(st + 10240 + rr, al[mf]);
            }
#pragma unroll
            for (int g = 0; g < 4; ++g) {
                uint32_t rr = (wn + g * 16 + b_row) * 80 + ko + b_coff;
                ldsm4(st + 20480 + rr, bb[g]);
            }
            // hi * hi
#pragma unroll
            for (int mf = 0; mf < 2; ++mf)
#pragma unroll
                for (int nf = 0; nf < 8; ++nf)
                    mma16816(acc[mf][nf], ah[mf], &bb[nf >> 1][(nf & 1) * 2]);
            // lo * hi
#pragma unroll
            for (int mf = 0; mf < 2; ++mf)
#pragma unroll
                for (int nf = 0; nf < 8; ++nf)
                    mma16816(acc[mf][nf], al[mf], &bb[nf >> 1][(nf & 1) * 2]);
            // reload B with lo
#pragma unroll
            for (int g = 0; g < 4; ++g) {
                uint32_t rr = (wn + g * 16 + b_row) * 80 + ko + b_coff;
                ldsm4(st + 30720 + rr, bb[g]);
            }
            // hi * lo
#pragma unroll
            for (int mf = 0; mf < 2; ++mf)
#pragma unroll
                for (int nf = 0; nf < 8; ++nf)
                    mma16816(acc[mf][nf], ah[mf], &bb[nf >> 1][(nf & 1) * 2]);
        }
        __syncthreads();
    }

    // ---- epilogue: Gram -> distance, write tile (+ mirrored tile) ----------
#pragma unroll
    for (int mf = 0; mf < 2; ++mf) {
#pragma unroll
        for (int rg = 0; rg < 2; ++rg) {
            const int m = wm + mf * 16 + rg * 8 + (lane >> 2);
            const float sqi = s_sqi[m];
#pragma unroll
            for (int nf = 0; nf < 8; ++nf) {
                const int n = wn + nf * 8 + (lane & 3) * 2;
                float d0 = sqi + s_sqj[n]     - 2.f * acc[mf][nf][rg * 2];
                float d1 = sqi + s_sqj[n + 1] - 2.f * acc[mf][nf][rg * 2 + 1];
                acc[mf][nf][rg * 2]     = sqrtf(fmaxf(d0, 0.f));
                acc[mf][nf][rg * 2 + 1] = sqrtf(fmaxf(d1, 0.f));
            }
        }
    }

    // straight write: Dm[i0+m][j0+n]
#pragma unroll
    for (int mf = 0; mf < 2; ++mf)
#pragma unroll
        for (int rg = 0; rg < 2; ++rg) {
            const int m = wm + mf * 16 + rg * 8 + (lane >> 2);
#pragma unroll
            for (int nf = 0; nf < 8; ++nf) {
                const int n = wn + nf * 8 + (lane & 3) * 2;
                float2 v = make_float2(acc[mf][nf][rg * 2], acc[mf][nf][rg * 2 + 1]);
                *(float2*)(g_Dm + (size_t)(i0 + m) * NPTS + j0 + n) = v;
            }
        }

    if (bx != by) {
        __syncthreads();                 // pipeline smem reuse as transpose tile
        float* stile = (float*)dyns;     // [128][129]
#pragma unroll
        for (int mf = 0; mf < 2; ++mf)
#pragma unroll
            for (int rg = 0; rg < 2; ++rg) {
                const int m = wm + mf * 16 + rg * 8 + (lane >> 2);
#pragma unroll
                for (int nf = 0; nf < 8; ++nf) {
                    const int n = wn + nf * 8 + (lane & 3) * 2;
                    stile[m * 129 + n]     = acc[mf][nf][rg * 2];
                    stile[m * 129 + n + 1] = acc[mf][nf][rg * 2 + 1];
                }
            }
        __syncthreads();
        for (int k = tid; k < 128 * 128; k += 256) {
            const int n = k >> 7, m = k & 127;
            g_Dm[(size_t)(j0 + n) * NPTS + i0 + m] = stile[m * 129 + n];
        }
    }
}

// ---------------- phase C: per-row mining ----------------------------------
__global__ void __launch_bounds__(256) mine_kernel() {
    extern __shared__ float s_row[];                 // 8192 floats (32 KB)
    __shared__ __align__(16) unsigned char s_t[NPTS];
    __shared__ float s_rv[256];
    __shared__ int   s_ri[256];
    __shared__ float s_dp_sh;
    __shared__ float s_semv;
    __shared__ int   s_semj;

    const int tid = threadIdx.x;
    const int i   = blockIdx.x;

    const float4* src = (const float4*)(g_Dm + (size_t)i * NPTS);
    for (int k = tid; k < NPTS / 4; k += 256) ((float4*)s_row)[k] = src[k];
    const uint4* tsrc = (const uint4*)g_tgt;
    for (int k = tid; k < NPTS / 16; k += 256) ((uint4*)s_t)[k] = tsrc[k];
    __syncthreads();

    const int ti = s_t[i];

    // pass 1: hardest positive (argmax, first index on tie)
    float bv = -1e30f; int bi = 0;
    for (int j = tid; j < NPTS; j += 256) {
        if (s_t[j] == ti && j != i) {
            float v = s_row[j];
            if (v > bv) { bv = v; bi = j; }
        }
    }
    s_rv[tid] = bv; s_ri[tid] = bi; __syncthreads();
    for (int s = 128; s; s >>= 1) {
        if (tid < s) {
            float v2 = s_rv[tid + s]; int j2 = s_ri[tid + s];
            if (v2 > s_rv[tid] || (v2 == s_rv[tid] && j2 < s_ri[tid])) {
                s_rv[tid] = v2; s_ri[tid] = j2;
            }
        }
        __syncthreads();
    }
    if (tid == 0) { g_pos[i] = s_ri[0]; s_dp_sh = s_rv[0]; }
    __syncthreads();
    const float dp = s_dp_sh;

    // pass 2: semi-hard (min in (dp, dp+1)) and overall-hardest negatives
    float hv = 1e30f; int hj = 0;
    float sv = 1e30f; int sj = 0;
    for (int j = tid; j < NPTS; j += 256) {
        if (s_t[j] != ti) {
            float v = s_row[j];
            if (v < hv) { hv = v; hj = j; }
            if (v > dp && v < dp + 1.0f && v < sv) { sv = v; sj = j; }
        }
    }
    s_rv[tid] = sv; s_ri[tid] = sj; __syncthreads();
    for (int s = 128; s; s >>= 1) {
        if (tid < s) {
            float v2 = s_rv[tid + s]; int j2 = s_ri[tid + s];
            if (v2 < s_rv[tid] || (v2 == s_rv[tid] && j2 < s_ri[tid])) {
                s_rv[tid] = v2; s_ri[tid] = j2;
            }
        }
        __syncthreads();
    }
    if (tid == 0) { s_semv = s_rv[0]; s_semj = s_ri[0]; }
    __syncthreads();
    s_rv[tid] = hv; s_ri[tid] = hj; __syncthreads();
    for (int s = 128; s; s >>= 1) {
        if (tid < s) {
            float v2 = s_rv[tid + s]; int j2 = s_ri[tid + s];
            if (v2 < s_rv[tid] || (v2 == s_rv[tid] && j2 < s_ri[tid])) {
                s_rv[tid] = v2; s_ri[tid] = j2;
            }
        }
        __syncthreads();
    }
    if (tid == 0) {
        g_neg[i] = (s_semv < 1e29f) ? s_semj : s_ri[0];
    }
}

// ---------------- phase D: exact per-anchor loss ---------------------------
__global__ void __launch_bounds__(256) loss_kernel(const float* __restrict__ emb) {
    const int i = blockIdx.x, tid = threadIdx.x;
    const float4* a = (const float4*)(emb + (size_t)i * DEMB);
    const float4* p = (const float4*)(emb + (size_t)g_pos[i] * DEMB);
    const float4* n = (const float4*)(emb + (size_t)g_neg[i] * DEMB);
    const float EPSC = 1e-6f;
    float4 av = a[tid], pv = p[tid], nv = n[tid];
    float sp = 0.f, sn = 0.f, t;
    t = av.x - pv.x + EPSC; sp += t * t;
    t = av.y - pv.y + EPSC; sp += t * t;
    t = av.z - pv.z + EPSC; sp += t * t;
    t = av.w - pv.w + EPSC; sp += t * t;
    t = av.x - nv.x + EPSC; sn += t * t;
    t = av.y - nv.y + EPSC; sn += t * t;
    t = av.z - nv.z + EPSC; sn += t * t;
    t = av.w - nv.w + EPSC; sn += t * t;
#pragma unroll
    for (int o = 16; o; o >>= 1) {
        sp += __shfl_down_sync(0xffffffffu, sp, o);
        sn += __shfl_down_sync(0xffffffffu, sn, o);
    }
    __shared__ float rp[8], rn[8];
    const int wid = tid >> 5, lid = tid & 31;
    if (lid == 0) { rp[wid] = sp; rn[wid] = sn; }
    __syncthreads();
    if (tid == 0) {
        float SP = 0.f, SN = 0.f;
#pragma unroll
        for (int w = 0; w < 8; w++) { SP += rp[w]; SN += rn[w]; }
        g_loss[i] = fmaxf(0.f, sqrtf(SP) - sqrtf(SN) + 1.0f);
    }
}

// ---------------- final: deterministic mean --------------------------------
__global__ void __launch_bounds__(256) reduce_kernel(float* __restrict__ out) {
    __shared__ float sb[256];
    const int tid = threadIdx.x;
    float s = 0.f;
    for (int j = tid; j < NPTS; j += 256) s += g_loss[j];
    sb[tid] = s; __syncthreads();
    for (int k = 128; k; k >>= 1) {
        if (tid < k) sb[tid] += sb[tid + k];
        __syncthreads();
    }
    if (tid == 0) out[0] = sb[0] / (float)NPTS;
}

// ---------------- launch ----------------------------------------------------
extern "C" void kernel_launch(void* const* d_in, const int* in_sizes, int n_in,
                              void* d_out, int out_size) {
    const float* emb = (const float*)d_in[0];
    const int*   tgt = (const int*)d_in[1];
    float*       out = (float*)d_out;

    cudaFuncSetAttribute(gemm_kernel, cudaFuncAttributeMaxDynamicSharedMemorySize, 82048);

    conv_kernel<<<(NPTS * DEMB) / 256, 256>>>(emb);
    sq_kernel<<<NPTS / 8, 256>>>(emb, tgt);
    gemm_kernel<<<NTILES, 256, 82048>>>();
    mine_kernel<<<NPTS, 256, NPTS * (int)sizeof(float)>>>();
    loss_kernel<<<NPTS, 256>>>(emb);
    reduce_kernel<<<1, 256>>>(out);
}